// round 1
// baseline (speedup 1.0000x reference)
#include <cuda_runtime.h>
#include <math.h>
#include <complex>

#ifndef M_PI
#define M_PI 3.14159265358979323846
#endif

#define NB 32
#define NT 300
#define NC 3
#define HW 5184        // 72*72
#define TS 270         // NT - 30
#define WW 29          // window length - 1

struct FiltParams {
    float inv_al[NT];  // 1/alpha of banded Cholesky
    float be[NT];      // L[i,i-1]
    float ga[NT];      // L[i,i-2]
    float fb[6];       // butter numerator
    float fa[6];       // butter denominator (fa[0]=1)
    float fzi[5];      // lfilter_zi
};

// ---------------- scratch (static device globals; no allocation) ----------------
__device__ float g_m[NB * NT * NC];
__device__ float g_Pn[NB * TS * 32];   // w padded 29->32
__device__ float g_Hs[NB * NT];

// ---------------- helpers ----------------
__device__ __forceinline__ float wsum(float v) {
#pragma unroll
    for (int o = 16; o; o >>= 1) v += __shfl_xor_sync(0xffffffffu, v, o);
    return v;
}

// ---------------- kernel 1: spatial mean over 72x72 per (b,t,c) ----------------
__global__ void k_mean(const float* __restrict__ x) {
    int s = blockIdx.x;  // 0 .. NB*NT*NC-1, c fastest
    const float4* p = reinterpret_cast<const float4*>(x) + (size_t)s * (HW / 4);
    float acc = 0.f;
    for (int i = threadIdx.x; i < HW / 4; i += blockDim.x) {
        float4 v = p[i];
        acc += (v.x + v.y) + (v.z + v.w);
    }
    acc = wsum(acc);
    __shared__ float sh[8];
    int lane = threadIdx.x & 31, wid = threadIdx.x >> 5;
    if (lane == 0) sh[wid] = acc;
    __syncthreads();
    if (threadIdx.x < 8) {
        float v = sh[threadIdx.x];
#pragma unroll
        for (int o = 4; o; o >>= 1) v += __shfl_xor_sync(0xffu, v, o);
        if (threadIdx.x == 0) g_m[s] = v * (1.f / (float)HW);
    }
}

// ---------------- kernel 2: POS per-window -> Pn ----------------
__global__ void k_pos() {
    int gw = (blockIdx.x * blockDim.x + threadIdx.x) >> 5;  // one warp per (b,t)
    int lane = threadIdx.x & 31;
    if (gw >= NB * TS) return;
    int b = gw / TS, t = gw - b * TS;

    bool act = lane < WW;
    float c0 = 0.f, c1 = 0.f, c2 = 0.f;
    if (act) {
        const float* p = g_m + ((b * NT) + (t + lane)) * NC;
        c0 = p[0]; c1 = p[1]; c2 = p[2];
    }
    const float invw = 1.0f / (float)WW;
    float mu0 = wsum(c0) * invw;
    float mu1 = wsum(c1) * invw;
    float mu2 = wsum(c2) * invw;
    float n0 = c0 / mu0, n1 = c1 / mu1, n2 = c2 / mu2;
    float s0 = act ? (n1 - n2) : 0.f;
    float s1 = act ? (n1 + n2 - 2.f * n0) : 0.f;
    float m0 = wsum(s0) * invw;
    float m1 = wsum(s1) * invw;
    float d0 = act ? (s0 - m0) : 0.f;
    float d1 = act ? (s1 - m1) : 0.f;
    float v0 = wsum(d0 * d0) * invw;
    float v1 = wsum(d1 * d1) * invw;
    float alpha = sqrtf(v0) / sqrtf(v1);
    float P = s0 + alpha * s1;  // valid for act lanes
    float mp = wsum(act ? P : 0.f) * invw;
    float dp = act ? (P - mp) : 0.f;
    float vp = wsum(dp * dp) * invw;
    float pn = dp / sqrtf(vp);
    g_Pn[gw * 32 + lane] = act ? pn : 0.f;
}

// ---------------- kernel 3: overlap-add via gather ----------------
__global__ void k_hs() {
    int i = blockIdx.x * blockDim.x + threadIdx.x;
    if (i >= NB * NT) return;
    int b = i / NT, tau = i - b * NT;
    int tlo = tau - (WW - 1); if (tlo < 0) tlo = 0;
    int thi = tau; if (thi > TS - 1) thi = TS - 1;
    float s = 0.f;
    for (int t = tlo; t <= thi; t++) s += g_Pn[(b * TS + t) * 32 + (tau - t)];
    g_Hs[i] = s;
}

// ---------------- kernel 4: detrend (IR pentadiagonal solve) + filtfilt + minmax --
__device__ __forceinline__ double A_diag(int i) {
    double dd = (i == 0 || i == NT - 1) ? 1.0 : ((i == 1 || i == NT - 2) ? 5.0 : 6.0);
    return 1.0 + 10000.0 * dd;
}
__device__ __forceinline__ double A_e(int i) {  // A[i][i-1], valid for i>=1
    return 10000.0 * ((i == 1 || i == NT - 1) ? -2.0 : -4.0);
}

__global__ void k_post(float* __restrict__ out, FiltParams P) {
    int b = threadIdx.x;
    if (b >= NB) return;
    const float* h = g_Hs + b * NT;

    // ---- solve A y = h via float Cholesky sweeps + fp64 iterative refinement ----
    double y[NT];
    float t[NT];
    for (int i = 0; i < NT; i++) y[i] = 0.0;

    for (int it = 0; it < 4; it++) {
        // residual r = h - A y  (double), rounded into t
        for (int i = 0; i < NT; i++) {
            double acc = (double)h[i];
            acc -= A_diag(i) * y[i];
            if (i >= 1)      acc -= A_e(i) * y[i - 1];
            if (i <= NT - 2) acc -= A_e(i + 1) * y[i + 1];
            if (i >= 2)      acc -= 10000.0 * y[i - 2];
            if (i <= NT - 3) acc -= 10000.0 * y[i + 2];
            t[i] = (float)acc;
        }
        // forward: L v = r
        float vm1 = 0.f, vm2 = 0.f;
        for (int i = 0; i < NT; i++) {
            float v = (t[i] - P.be[i] * vm1 - P.ga[i] * vm2) * P.inv_al[i];
            t[i] = v; vm2 = vm1; vm1 = v;
        }
        // backward: L^T c = v  (in place)
        float cp1 = 0.f, cp2 = 0.f;
        for (int i = NT - 1; i >= 0; i--) {
            float bn = (i < NT - 1) ? P.be[i + 1] * cp1 : 0.f;
            float gn = (i < NT - 2) ? P.ga[i + 2] * cp2 : 0.f;
            float c = (t[i] - bn - gn) * P.inv_al[i];
            t[i] = c; cp2 = cp1; cp1 = c;
        }
        for (int i = 0; i < NT; i++) y[i] += (double)t[i];
    }

    float df[NT];
    for (int i = 0; i < NT; i++) df[i] = h[i] - (float)y[i];

    // ---- filtfilt (padlen = 18, ext length 336) ----
    const int PAD = 18, EXT = NT + 2 * PAD;  // 336
    float y1[EXT];
    float z0, z1, z2, z3, z4;

    // pass 1 forward over ext
    {
        float x0 = 2.f * df[0] - df[PAD];  // ext[0]
        z0 = P.fzi[0] * x0; z1 = P.fzi[1] * x0; z2 = P.fzi[2] * x0;
        z3 = P.fzi[3] * x0; z4 = P.fzi[4] * x0;
        for (int j = 0; j < EXT; j++) {
            float xt;
            if (j < PAD)            xt = 2.f * df[0] - df[PAD - j];
            else if (j < PAD + NT)  xt = df[j - PAD];
            else                    xt = 2.f * df[NT - 1] - df[NT - 2 - (j - PAD - NT)];
            float yv = P.fb[0] * xt + z0;
            z0 = z1 + P.fb[1] * xt - P.fa[1] * yv;
            z1 = z2 + P.fb[2] * xt - P.fa[2] * yv;
            z2 = z3 + P.fb[3] * xt - P.fa[3] * yv;
            z3 = z4 + P.fb[4] * xt - P.fa[4] * yv;
            z4 =      P.fb[5] * xt - P.fa[5] * yv;
            y1[j] = yv;
        }
    }

    // pass 2 over reversed y1; keep trimmed result f[i] = y2[317 - i]
    float f[NT];
    float mn = 3.0e38f, mx = -3.0e38f;
    {
        float x0 = y1[EXT - 1];
        z0 = P.fzi[0] * x0; z1 = P.fzi[1] * x0; z2 = P.fzi[2] * x0;
        z3 = P.fzi[3] * x0; z4 = P.fzi[4] * x0;
        for (int j = 0; j < EXT; j++) {
            float xt = y1[EXT - 1 - j];
            float yv = P.fb[0] * xt + z0;
            z0 = z1 + P.fb[1] * xt - P.fa[1] * yv;
            z1 = z2 + P.fb[2] * xt - P.fa[2] * yv;
            z2 = z3 + P.fb[3] * xt - P.fa[3] * yv;
            z3 = z4 + P.fb[4] * xt - P.fa[4] * yv;
            z4 =      P.fb[5] * xt - P.fa[5] * yv;
            int i = (PAD + NT - 1) - j;  // 317 - j
            if (i >= 0 && i < NT) {
                f[i] = yv;
                mn = fminf(mn, yv);
                mx = fmaxf(mx, yv);
            }
        }
    }

    float inv = 1.f / (mx - mn);
    for (int i = 0; i < NT; i++) out[b * NT + i] = (f[i] - mn) * inv;
}

// ---------------- host-side constant computation (capture-time, deterministic) ---
static void compute_params(FiltParams& FP) {
    // banded Cholesky of A = I + lam^2 D^T D (double)
    const double L2 = 10000.0;
    double dgl[NT], eb[NT], al[NT], be[NT], ga[NT];
    for (int i = 0; i < NT; i++) {
        double dd = (i == 0 || i == NT - 1) ? 1.0 : ((i == 1 || i == NT - 2) ? 5.0 : 6.0);
        dgl[i] = 1.0 + L2 * dd;
        eb[i]  = (i == 0) ? 0.0 : L2 * ((i == 1 || i == NT - 1) ? -2.0 : -4.0);
    }
    for (int i = 0; i < NT; i++) {
        double g = (i >= 2) ? (L2 / al[i - 2]) : 0.0;
        double bb = (i >= 1) ? ((eb[i] - g * be[i - 1]) / al[i - 1]) : 0.0;
        double a = sqrt(dgl[i] - g * g - bb * bb);
        ga[i] = g; be[i] = bb; al[i] = a;
        FP.ga[i] = (float)g; FP.be[i] = (float)bb; FP.inv_al[i] = (float)(1.0 / a);
    }

    // Butterworth order 5, wn = 0.2 (matches reference formulas, double precision)
    using cd = std::complex<double>;
    const int ORD = 5;
    double wn = 3.0 / 15.0;
    double warped = 4.0 * tan(M_PI * wn / 2.0);
    cd p[ORD];
    for (int k = 1; k <= ORD; k++) {
        double ang = M_PI * (2.0 * k + ORD - 1.0) / (2.0 * ORD);
        p[k - 1] = warped * std::exp(cd(0.0, ang));
    }
    double kg = pow(warped, (double)ORD);
    cd pz[ORD];
    cd prod(1.0, 0.0);
    for (int k = 0; k < ORD; k++) {
        pz[k] = (4.0 + p[k]) / (4.0 - p[k]);
        prod *= (4.0 - p[k]);
    }
    double kz = kg * std::real(1.0 / prod);
    const double binom[6] = {1, 5, 10, 10, 5, 1};
    double bcoef[6], acoef[6];
    for (int i = 0; i < 6; i++) bcoef[i] = kz * binom[i];
    // poly(pz), monic
    cd ac[6];
    ac[0] = cd(1.0, 0.0);
    for (int i = 1; i < 6; i++) ac[i] = cd(0.0, 0.0);
    for (int k = 0; k < ORD; k++)
        for (int j = k + 1; j >= 1; j--) ac[j] = ac[j] - pz[k] * ac[j - 1];
    for (int i = 0; i < 6; i++) acoef[i] = std::real(ac[i]);

    // lfilter_zi: solve (I - comp^T) zi = B, 5x5
    double comp[5][5] = {};
    for (int j = 0; j < 5; j++) comp[0][j] = -acoef[j + 1] / acoef[0];
    for (int i = 1; i < 5; i++) comp[i][i - 1] = 1.0;
    double A5[5][6];
    for (int i = 0; i < 5; i++) {
        for (int j = 0; j < 5; j++) A5[i][j] = ((i == j) ? 1.0 : 0.0) - comp[j][i];
        A5[i][5] = bcoef[i + 1] - acoef[i + 1] * bcoef[0];
    }
    // Gaussian elimination with partial pivoting
    for (int c = 0; c < 5; c++) {
        int piv = c;
        for (int r = c + 1; r < 5; r++)
            if (fabs(A5[r][c]) > fabs(A5[piv][c])) piv = r;
        if (piv != c)
            for (int j = 0; j < 6; j++) { double tmp = A5[c][j]; A5[c][j] = A5[piv][j]; A5[piv][j] = tmp; }
        for (int r = c + 1; r < 5; r++) {
            double fct = A5[r][c] / A5[c][c];
            for (int j = c; j < 6; j++) A5[r][j] -= fct * A5[c][j];
        }
    }
    double zi[5];
    for (int r = 4; r >= 0; r--) {
        double s = A5[r][5];
        for (int j = r + 1; j < 5; j++) s -= A5[r][j] * zi[j];
        zi[r] = s / A5[r][r];
    }

    for (int i = 0; i < 6; i++) { FP.fb[i] = (float)bcoef[i]; FP.fa[i] = (float)acoef[i]; }
    for (int i = 0; i < 5; i++) FP.fzi[i] = (float)zi[i];
}

// ---------------- launch ----------------
extern "C" void kernel_launch(void* const* d_in, const int* in_sizes, int n_in,
                              void* d_out, int out_size) {
    const float* x = (const float*)d_in[0];
    float* out = (float*)d_out;

    FiltParams FP;
    compute_params(FP);

    k_mean<<<NB * NT * NC, 256>>>(x);
    k_pos<<<(NB * TS * 32 + 127) / 128, 128>>>();
    k_hs<<<(NB * NT + 127) / 128, 128>>>();
    k_post<<<1, NB>>>(out, FP);
}

// round 2
// speedup vs baseline: 3.8869x; 3.8869x over previous
#include <cuda_runtime.h>
#include <math.h>
#include <complex>

#ifndef M_PI
#define M_PI 3.14159265358979323846
#endif

#define NB 32
#define NT 300
#define NC 3
#define HW 5184        // 72*72
#define TS 270         // NT - 30
#define WW 29          // window length - 1
#define PAD 18
#define EXT (NT + 2 * PAD)   // 336

struct FiltParams {
    float inv_al[NT];  // 1/alpha of banded Cholesky
    float be[NT];      // L[i,i-1]
    float ga[NT];      // L[i,i-2]
    float fb[6];       // butter numerator
    float fa[6];       // butter denominator (fa[0]=1)
    float fzi[5];      // lfilter_zi
};

// ---------------- scratch (static device globals; no allocation) ----------------
__device__ float g_m[NB * NT * NC];
__device__ float g_Pn[NB * TS * 32];   // w padded 29->32
__device__ float g_Hs[NB * NT];

// ---------------- helpers ----------------
__device__ __forceinline__ float wsum(float v) {
#pragma unroll
    for (int o = 16; o; o >>= 1) v += __shfl_xor_sync(0xffffffffu, v, o);
    return v;
}

// ---------------- kernel 1: spatial mean over 72x72 per (b,t,c) ----------------
__global__ void k_mean(const float* __restrict__ x) {
    int s = blockIdx.x;  // 0 .. NB*NT*NC-1, c fastest
    const float4* p = reinterpret_cast<const float4*>(x) + (size_t)s * (HW / 4);
    float acc = 0.f;
    for (int i = threadIdx.x; i < HW / 4; i += blockDim.x) {
        float4 v = p[i];
        acc += (v.x + v.y) + (v.z + v.w);
    }
    acc = wsum(acc);
    __shared__ float sh[8];
    int lane = threadIdx.x & 31, wid = threadIdx.x >> 5;
    if (lane == 0) sh[wid] = acc;
    __syncthreads();
    if (threadIdx.x < 8) {
        float v = sh[threadIdx.x];
#pragma unroll
        for (int o = 4; o; o >>= 1) v += __shfl_xor_sync(0xffu, v, o);
        if (threadIdx.x == 0) g_m[s] = v * (1.f / (float)HW);
    }
}

// ---------------- kernel 2: POS per-window -> Pn ----------------
__global__ void k_pos() {
    int gw = (blockIdx.x * blockDim.x + threadIdx.x) >> 5;  // one warp per (b,t)
    int lane = threadIdx.x & 31;
    if (gw >= NB * TS) return;
    int b = gw / TS, t = gw - b * TS;

    bool act = lane < WW;
    float c0 = 0.f, c1 = 0.f, c2 = 0.f;
    if (act) {
        const float* p = g_m + ((b * NT) + (t + lane)) * NC;
        c0 = p[0]; c1 = p[1]; c2 = p[2];
    }
    const float invw = 1.0f / (float)WW;
    float mu0 = wsum(c0) * invw;
    float mu1 = wsum(c1) * invw;
    float mu2 = wsum(c2) * invw;
    float n0 = c0 / mu0, n1 = c1 / mu1, n2 = c2 / mu2;
    float s0 = act ? (n1 - n2) : 0.f;
    float s1 = act ? (n1 + n2 - 2.f * n0) : 0.f;
    float m0 = wsum(s0) * invw;
    float m1 = wsum(s1) * invw;
    float d0 = act ? (s0 - m0) : 0.f;
    float d1 = act ? (s1 - m1) : 0.f;
    float v0 = wsum(d0 * d0) * invw;
    float v1 = wsum(d1 * d1) * invw;
    float alpha = sqrtf(v0) / sqrtf(v1);
    float P = s0 + alpha * s1;  // valid for act lanes
    float mp = wsum(act ? P : 0.f) * invw;
    float dp = act ? (P - mp) : 0.f;
    float vp = wsum(dp * dp) * invw;
    float pn = dp / sqrtf(vp);
    g_Pn[gw * 32 + lane] = act ? pn : 0.f;
}

// ---------------- kernel 3: overlap-add via gather ----------------
__global__ void k_hs() {
    int i = blockIdx.x * blockDim.x + threadIdx.x;
    if (i >= NB * NT) return;
    int b = i / NT, tau = i - b * NT;
    int tlo = tau - (WW - 1); if (tlo < 0) tlo = 0;
    int thi = tau; if (thi > TS - 1) thi = TS - 1;
    float s = 0.f;
    for (int t = tlo; t <= thi; t++) s += g_Pn[(b * TS + t) * 32 + (tau - t)];
    g_Hs[i] = s;
}

// ---------------- kernel 4: detrend + filtfilt + minmax, one warp per row -------
__device__ __forceinline__ double A_diag(int i) {
    double dd = (i == 0 || i == NT - 1) ? 1.0 : ((i == 1 || i == NT - 2) ? 5.0 : 6.0);
    return 1.0 + 10000.0 * dd;
}
__device__ __forceinline__ double A_e(int i) {  // A[i][i-1], valid for i>=1
    return 10000.0 * ((i == 1 || i == NT - 1) ? -2.0 : -4.0);
}

__global__ void __launch_bounds__(32) k_post(float* __restrict__ out, FiltParams P) {
    __shared__ float  sh_h[NT];
    __shared__ float  sh_t[NT];
    __shared__ float  sh_df[NT];
    __shared__ float  sh_y1[EXT];
    __shared__ float  sh_f[NT];
    __shared__ double sh_y[NT];

    const int b = blockIdx.x;
    const int lane = threadIdx.x;

    // load Hs row; init y = 0
    for (int i = lane; i < NT; i += 32) {
        sh_h[i] = g_Hs[b * NT + i];
        sh_y[i] = 0.0;
    }
    __syncwarp();

    // ---- iterative refinement: float substitution sweeps + fp64 residual -------
    for (int it = 0; it < 3; it++) {
        // residual r = h - A y  (fp64, parallel across lanes)
        for (int i = lane; i < NT; i += 32) {
            double acc = (double)sh_h[i];
            acc -= A_diag(i) * sh_y[i];
            if (i >= 1)      acc -= A_e(i) * sh_y[i - 1];
            if (i <= NT - 2) acc -= A_e(i + 1) * sh_y[i + 1];
            if (i >= 2)      acc -= 10000.0 * sh_y[i - 2];
            if (i <= NT - 3) acc -= 10000.0 * sh_y[i + 2];
            sh_t[i] = (float)acc;
        }
        __syncwarp();
        // serial substitutions on lane 0 (float, coeffs from constant memory)
        if (lane == 0) {
            float vm1 = 0.f, vm2 = 0.f;
            for (int i = 0; i < NT; i++) {
                float v = (sh_t[i] - P.be[i] * vm1 - P.ga[i] * vm2) * P.inv_al[i];
                sh_t[i] = v; vm2 = vm1; vm1 = v;
            }
            float cp1 = 0.f, cp2 = 0.f;
            for (int i = NT - 1; i >= 0; i--) {
                float bn = (i < NT - 1) ? P.be[i + 1] * cp1 : 0.f;
                float gn = (i < NT - 2) ? P.ga[i + 2] * cp2 : 0.f;
                float c = (sh_t[i] - bn - gn) * P.inv_al[i];
                sh_t[i] = c; cp2 = cp1; cp1 = c;
            }
        }
        __syncwarp();
        for (int i = lane; i < NT; i += 32) sh_y[i] += (double)sh_t[i];
        __syncwarp();
    }

    // detrended signal
    for (int i = lane; i < NT; i += 32) sh_df[i] = sh_h[i] - (float)sh_y[i];
    __syncwarp();

    // ---- filtfilt (lane 0, serial scans over smem) ------------------------------
    float mn = 3.0e38f, mx = -3.0e38f;
    if (lane == 0) {
        float z0, z1, z2, z3, z4;
        // pass 1 forward over extended signal
        {
            float x0 = 2.f * sh_df[0] - sh_df[PAD];  // ext[0]
            z0 = P.fzi[0] * x0; z1 = P.fzi[1] * x0; z2 = P.fzi[2] * x0;
            z3 = P.fzi[3] * x0; z4 = P.fzi[4] * x0;
            for (int j = 0; j < EXT; j++) {
                float xt;
                if (j < PAD)            xt = 2.f * sh_df[0] - sh_df[PAD - j];
                else if (j < PAD + NT)  xt = sh_df[j - PAD];
                else                    xt = 2.f * sh_df[NT - 1] - sh_df[NT - 2 - (j - PAD - NT)];
                float yv = P.fb[0] * xt + z0;
                z0 = z1 + P.fb[1] * xt - P.fa[1] * yv;
                z1 = z2 + P.fb[2] * xt - P.fa[2] * yv;
                z2 = z3 + P.fb[3] * xt - P.fa[3] * yv;
                z3 = z4 + P.fb[4] * xt - P.fa[4] * yv;
                z4 =      P.fb[5] * xt - P.fa[5] * yv;
                sh_y1[j] = yv;
            }
        }
        // pass 2 over reversed y1; keep trimmed result f[i] = y2[317 - i]
        {
            float x0 = sh_y1[EXT - 1];
            z0 = P.fzi[0] * x0; z1 = P.fzi[1] * x0; z2 = P.fzi[2] * x0;
            z3 = P.fzi[3] * x0; z4 = P.fzi[4] * x0;
            for (int j = 0; j < EXT; j++) {
                float xt = sh_y1[EXT - 1 - j];
                float yv = P.fb[0] * xt + z0;
                z0 = z1 + P.fb[1] * xt - P.fa[1] * yv;
                z1 = z2 + P.fb[2] * xt - P.fa[2] * yv;
                z2 = z3 + P.fb[3] * xt - P.fa[3] * yv;
                z3 = z4 + P.fb[4] * xt - P.fa[4] * yv;
                z4 =      P.fb[5] * xt - P.fa[5] * yv;
                int i = (PAD + NT - 1) - j;  // 317 - j
                if (i >= 0 && i < NT) {
                    sh_f[i] = yv;
                    mn = fminf(mn, yv);
                    mx = fmaxf(mx, yv);
                }
            }
        }
    }
    // broadcast min/max, normalize in parallel
    mn = __shfl_sync(0xffffffffu, mn, 0);
    mx = __shfl_sync(0xffffffffu, mx, 0);
    __syncwarp();
    float inv = 1.f / (mx - mn);
    for (int i = lane; i < NT; i += 32) out[b * NT + i] = (sh_f[i] - mn) * inv;
}

// ---------------- host-side constant computation (capture-time, deterministic) ---
static void compute_params(FiltParams& FP) {
    // banded Cholesky of A = I + lam^2 D^T D (double)
    const double L2 = 10000.0;
    double dgl[NT], eb[NT], al[NT], be[NT], ga[NT];
    for (int i = 0; i < NT; i++) {
        double dd = (i == 0 || i == NT - 1) ? 1.0 : ((i == 1 || i == NT - 2) ? 5.0 : 6.0);
        dgl[i] = 1.0 + L2 * dd;
        eb[i]  = (i == 0) ? 0.0 : L2 * ((i == 1 || i == NT - 1) ? -2.0 : -4.0);
    }
    for (int i = 0; i < NT; i++) {
        double g = (i >= 2) ? (L2 / al[i - 2]) : 0.0;
        double bb = (i >= 1) ? ((eb[i] - g * be[i - 1]) / al[i - 1]) : 0.0;
        double a = sqrt(dgl[i] - g * g - bb * bb);
        ga[i] = g; be[i] = bb; al[i] = a;
        FP.ga[i] = (float)g; FP.be[i] = (float)bb; FP.inv_al[i] = (float)(1.0 / a);
    }

    // Butterworth order 5, wn = 0.2 (matches reference formulas, double precision)
    using cd = std::complex<double>;
    const int ORD = 5;
    double wn = 3.0 / 15.0;
    double warped = 4.0 * tan(M_PI * wn / 2.0);
    cd p[ORD];
    for (int k = 1; k <= ORD; k++) {
        double ang = M_PI * (2.0 * k + ORD - 1.0) / (2.0 * ORD);
        p[k - 1] = warped * std::exp(cd(0.0, ang));
    }
    double kg = pow(warped, (double)ORD);
    cd pz[ORD];
    cd prod(1.0, 0.0);
    for (int k = 0; k < ORD; k++) {
        pz[k] = (4.0 + p[k]) / (4.0 - p[k]);
        prod *= (4.0 - p[k]);
    }
    double kz = kg * std::real(1.0 / prod);
    const double binom[6] = {1, 5, 10, 10, 5, 1};
    double bcoef[6], acoef[6];
    for (int i = 0; i < 6; i++) bcoef[i] = kz * binom[i];
    // poly(pz), monic
    cd ac[6];
    ac[0] = cd(1.0, 0.0);
    for (int i = 1; i < 6; i++) ac[i] = cd(0.0, 0.0);
    for (int k = 0; k < ORD; k++)
        for (int j = k + 1; j >= 1; j--) ac[j] = ac[j] - pz[k] * ac[j - 1];
    for (int i = 0; i < 6; i++) acoef[i] = std::real(ac[i]);

    // lfilter_zi: solve (I - comp^T) zi = B, 5x5
    double comp[5][5] = {};
    for (int j = 0; j < 5; j++) comp[0][j] = -acoef[j + 1] / acoef[0];
    for (int i = 1; i < 5; i++) comp[i][i - 1] = 1.0;
    double A5[5][6];
    for (int i = 0; i < 5; i++) {
        for (int j = 0; j < 5; j++) A5[i][j] = ((i == j) ? 1.0 : 0.0) - comp[j][i];
        A5[i][5] = bcoef[i + 1] - acoef[i + 1] * bcoef[0];
    }
    // Gaussian elimination with partial pivoting
    for (int c = 0; c < 5; c++) {
        int piv = c;
        for (int r = c + 1; r < 5; r++)
            if (fabs(A5[r][c]) > fabs(A5[piv][c])) piv = r;
        if (piv != c)
            for (int j = 0; j < 6; j++) { double tmp = A5[c][j]; A5[c][j] = A5[piv][j]; A5[piv][j] = tmp; }
        for (int r = c + 1; r < 5; r++) {
            double fct = A5[r][c] / A5[c][c];
            for (int j = c; j < 6; j++) A5[r][j] -= fct * A5[c][j];
        }
    }
    double zi[5];
    for (int r = 4; r >= 0; r--) {
        double s = A5[r][5];
        for (int j = r + 1; j < 5; j++) s -= A5[r][j] * zi[j];
        zi[r] = s / A5[r][r];
    }

    for (int i = 0; i < 6; i++) { FP.fb[i] = (float)bcoef[i]; FP.fa[i] = (float)acoef[i]; }
    for (int i = 0; i < 5; i++) FP.fzi[i] = (float)zi[i];
}

// ---------------- launch ----------------
extern "C" void kernel_launch(void* const* d_in, const int* in_sizes, int n_in,
                              void* d_out, int out_size) {
    const float* x = (const float*)d_in[0];
    float* out = (float*)d_out;

    FiltParams FP;
    compute_params(FP);

    k_mean<<<NB * NT * NC, 256>>>(x);
    k_pos<<<(NB * TS * 32 + 127) / 128, 128>>>();
    k_hs<<<(NB * NT + 127) / 128, 128>>>();
    k_post<<<NB, 32>>>(out, FP);
}